// round 2
// baseline (speedup 1.0000x reference)
#include <cuda_runtime.h>
#include <math.h>

#define NB 4          // batch / classes
#define DD 512        // feature dim
#define CCB 2         // compute blocks (256 columns each)
#define TPB 256
#define ALPHA_IT 0.7f
#define BETA_IT  0.5f

__global__ void __launch_bounds__(TPB)
graphlearner_fused(const float* __restrict__ bt,    // base_text_features (4,512)
                   const float* __restrict__ bi,    // base_img_features  (4,512)
                   const float* __restrict__ img,   // img_feature (40960,512)
                   const float* __restrict__ Wtt,   // (512,512)
                   const float* __restrict__ btt,   // (4,512)
                   const float* __restrict__ Wit,   // (512,512)
                   const float* __restrict__ bit_,  // (4,512)
                   float* __restrict__ out,         // refined(4,512) ++ img(40960,512)
                   long long n_img_f4)
{
    const int tid = threadIdx.x;

    // ---------------- copy blocks: stream img_feature -> out + 2048 --------
    if (blockIdx.x >= CCB) {
        const float4* __restrict__ src = (const float4*)img;
        float4* __restrict__ dst = (float4*)(out + NB * DD);
        const long long stride = (long long)(gridDim.x - CCB) * TPB;
        long long i = (long long)(blockIdx.x - CCB) * TPB + tid;

        // main loop: 4 independent in-flight float4 loads per iteration
        for (; i + 3 * stride < n_img_f4; i += 4 * stride) {
            float4 a0 = __ldcs(src + i);
            float4 a1 = __ldcs(src + i + stride);
            float4 a2 = __ldcs(src + i + 2 * stride);
            float4 a3 = __ldcs(src + i + 3 * stride);
            __stcs(dst + i,              a0);
            __stcs(dst + i + stride,     a1);
            __stcs(dst + i + 2 * stride, a2);
            __stcs(dst + i + 3 * stride, a3);
        }
        for (; i < n_img_f4; i += stride)
            __stcs(dst + i, __ldcs(src + i));
        return;
    }

    // ---------------- compute blocks (~16.5 KB smem) -----------------------
    __shared__ float bt_s[NB][DD];
    __shared__ float bi_s[NB][DD];
    __shared__ float raw[3][NB][NB];   // 0: bt.bt  1: bt.bi  2: bi.bi
    __shared__ float c_tt[NB][5];
    __shared__ float c_it[NB][5];

    for (int i = tid; i < NB * DD; i += TPB) {
        ((float*)bt_s)[i] = bt[i];
        ((float*)bi_s)[i] = bi[i];
    }
    __syncthreads();

    // 48 dot products (3 gram matrices, 4x4 each), one warp per dot, 8 warps
    {
        const int warp = tid >> 5, lane = tid & 31;
        for (int q = warp; q < 48; q += 8) {
            const int mat = q >> 4, i = (q & 15) >> 2, j = q & 3;
            const float* a = (mat == 2) ? bi_s[i] : bt_s[i];
            const float* c = (mat == 0) ? bt_s[j] : bi_s[j];
            float s = 0.f;
            for (int k = lane; k < DD; k += 32) s += a[k] * c[k];
            #pragma unroll
            for (int off = 16; off > 0; off >>= 1)
                s += __shfl_down_sync(0xffffffffu, s, off);
            if (lane == 0) raw[mat][i][j] = s;
        }
    }
    __syncthreads();

    // 8 tiny graphs: threads 0..3 -> tt for b, threads 4..7 -> it for b
    if (tid < 8) {
        const int b = tid & 3;
        const bool is_it = tid >= 4;
        float nt[NB], ni[NB];
        #pragma unroll
        for (int i = 0; i < NB; i++) {
            nt[i] = fmaxf(sqrtf(raw[0][i][i]), 1e-12f);
            ni[i] = fmaxf(sqrtf(raw[2][i][i]), 1e-12f);
        }
        float e[5][5];
        if (!is_it) {
            e[0][0] = raw[0][b][b] / (nt[b] * nt[b]);
            #pragma unroll
            for (int m = 1; m < 5; m++) {
                e[0][m] = raw[0][b][m - 1] / (nt[b] * nt[m - 1]);
                e[m][0] = raw[0][m - 1][b] / (nt[m - 1] * nt[b]);
            }
            #pragma unroll
            for (int n = 1; n < 5; n++)
                #pragma unroll
                for (int m = 1; m < 5; m++)
                    e[n][m] = raw[0][n - 1][m - 1] / (nt[n - 1] * nt[m - 1]);
        } else {
            e[0][0] = raw[0][b][b] / (nt[b] * nt[b]);
            #pragma unroll
            for (int m = 1; m < 5; m++) {
                e[0][m] = raw[1][b][m - 1] / (nt[b] * ni[m - 1]);
                e[m][0] = e[0][m];
            }
            #pragma unroll
            for (int n = 1; n < 5; n++)
                #pragma unroll
                for (int m = 1; m < 5; m++)
                    e[n][m] = raw[2][n - 1][m - 1] / (ni[n - 1] * ni[m - 1]);
        }
        float adj[5][5], deg[5];
        #pragma unroll
        for (int n = 0; n < 5; n++) {
            deg[n] = 0.f;
            #pragma unroll
            for (int m = 0; m < 5; m++) {
                adj[n][m] = fmaxf(e[n][m], 0.f) + ((n == m) ? 1.f : 0.f);
                deg[n] += adj[n][m];
            }
        }
        float dinv[5];
        #pragma unroll
        for (int n = 0; n < 5; n++)
            dinv[n] = (deg[n] > 0.f) ? (1.f / sqrtf(deg[n])) : 0.f;
        float* cc = is_it ? c_it[b] : c_tt[b];
        #pragma unroll
        for (int m = 0; m < 5; m++)
            cc[m] = dinv[0] * adj[0][m] * dinv[m];
    }
    __syncthreads();

    // dual GEMV with summation-order swap: 12 accumulators per column thread.
    //   u_tt[m]  = sum_k Wtt[k,d] * bt[m,k]
    //   u_itb[m] = sum_k Wit[k,d] * bt[m,k]
    //   u_iti[m] = sum_k Wit[k,d] * bi[m,k]
    const int d = blockIdx.x * TPB + tid;   // 0..511
    float u_tt[NB]  = {0.f, 0.f, 0.f, 0.f};
    float u_itb[NB] = {0.f, 0.f, 0.f, 0.f};
    float u_iti[NB] = {0.f, 0.f, 0.f, 0.f};
    #pragma unroll 4
    for (int k = 0; k < DD; k++) {
        const float wt = Wtt[k * DD + d];
        const float wi = Wit[k * DD + d];
        #pragma unroll
        for (int m = 0; m < NB; m++) {
            u_tt[m]  = fmaf(wt, bt_s[m][k], u_tt[m]);
            u_itb[m] = fmaf(wi, bt_s[m][k], u_itb[m]);
            u_iti[m] = fmaf(wi, bi_s[m][k], u_iti[m]);
        }
    }

    #pragma unroll
    for (int b = 0; b < NB; b++) {
        float att = c_tt[b][0] * u_tt[b];
        float ait = c_it[b][0] * u_itb[b];
        #pragma unroll
        for (int j = 0; j < NB; j++) {
            att = fmaf(c_tt[b][j + 1], u_tt[j],  att);
            ait = fmaf(c_it[b][j + 1], u_iti[j], ait);
        }
        const float stt = att + btt[b * DD + d];
        const float sit = ait + bit_[b * DD + d];
        const float g = ALPHA_IT * tanhf(stt) + (1.f - ALPHA_IT) * tanhf(sit);
        out[b * DD + d] = BETA_IT * bt_s[b][d] + (1.f - BETA_IT) * g;
    }
}

extern "C" void kernel_launch(void* const* d_in, const int* in_sizes, int n_in,
                              void* d_out, int out_size) {
    const float* bt   = (const float*)d_in[0];
    const float* bi   = (const float*)d_in[1];
    const float* img  = (const float*)d_in[2];
    const float* Wtt  = (const float*)d_in[3];
    const float* btt  = (const float*)d_in[4];
    const float* Wit  = (const float*)d_in[5];
    const float* bit_ = (const float*)d_in[6];
    float* out = (float*)d_out;

    const long long n_img    = (long long)in_sizes[2];   // 40960*512
    const long long n_img_f4 = n_img / 4;

    const int copy_blocks = 148 * 8;
    dim3 grid(CCB + copy_blocks), block(TPB);
    graphlearner_fused<<<grid, block>>>(bt, bi, img, Wtt, btt, Wit, bit_,
                                        out, n_img_f4);
}